// round 10
// baseline (speedup 1.0000x reference)
#include <cuda_runtime.h>
#include <cstdint>
#include <math.h>

#define T_TOK 1024
#define HDIM  2048
#define NEXP  32
#define IDIM  1408
#define ISH   5632
#define TOPK  4
#define CAP   256

__device__ int   g_counts[NEXP];
__device__ int   g_top_e[T_TOK*TOPK];
__device__ float g_top_w[T_TOK*TOPK];
__device__ int   g_slot_tok[NEXP*CAP];
__device__ float g_slot_w[NEXP*CAP];
__device__ float g_h[(size_t)NEXP*CAP*IDIM];   // expert intermediate (tf32-rounded)
__device__ float g_hs[(size_t)T_TOK*ISH];      // shared intermediate (tf32-rounded)
__device__ float g_xr[(size_t)T_TOK*HDIM];     // x rounded to tf32
__device__ float g_sgate[T_TOK];

// ---------------- helpers ----------------------------------------------------
__device__ __forceinline__ uint32_t f2tf(float x) {
    uint32_t r; asm("cvt.rna.tf32.f32 %0, %1;" : "=r"(r) : "f"(x)); return r;
}
__device__ __forceinline__ float rtf(float x) {
    return __uint_as_float(f2tf(x));
}
__device__ __forceinline__ void mma_m16n8k8(float c[4],
    uint32_t a0, uint32_t a1, uint32_t a2, uint32_t a3, uint32_t b0, uint32_t b1)
{
    asm volatile(
      "mma.sync.aligned.m16n8k8.row.col.f32.tf32.tf32.f32 "
      "{%0,%1,%2,%3},{%4,%5,%6,%7},{%8,%9},{%0,%1,%2,%3};\n"
      : "+f"(c[0]), "+f"(c[1]), "+f"(c[2]), "+f"(c[3])
      : "r"(a0), "r"(a1), "r"(a2), "r"(a3), "r"(b0), "r"(b1));
}
__device__ __forceinline__ void cp16(void* sdst, const void* gsrc, bool pred) {
    uint32_t s = (uint32_t)__cvta_generic_to_shared(sdst);
    int sz = pred ? 16 : 0;
    asm volatile("cp.async.cg.shared.global [%0], [%1], 16, %2;\n"
                 :: "r"(s), "l"(gsrc), "r"(sz));
}
#define LDSM4(r0,r1,r2,r3,a) \
    asm volatile("ldmatrix.sync.aligned.m8n8.x4.shared.b16 {%0,%1,%2,%3}, [%4];" \
        : "=r"(r0), "=r"(r1), "=r"(r2), "=r"(r3) : "r"(a))

// ---------------- small kernels ----------------------------------------------
__global__ void zero_counts_kernel() {
    if (threadIdx.x < NEXP) g_counts[threadIdx.x] = 0;
}

__global__ __launch_bounds__(256) void round_x_kernel(const float* __restrict__ x) {
    const int i = blockIdx.x * 256 + threadIdx.x;
    float4 v = reinterpret_cast<const float4*>(x)[i];
    v.x = rtf(v.x); v.y = rtf(v.y); v.z = rtf(v.z); v.w = rtf(v.w);
    reinterpret_cast<float4*>(g_xr)[i] = v;
}

__global__ __launch_bounds__(128) void router_kernel(
    const float* __restrict__ x, const float* __restrict__ gate_w,
    const float* __restrict__ wsg, float* __restrict__ logits_out)
{
    __shared__ float xs[HDIM];
    __shared__ float ls[NEXP];
    __shared__ float ps[NEXP];
    __shared__ float gred[4];
    const int t = blockIdx.x;
    const int tid = threadIdx.x;
    const float* xr = x + (size_t)t * HDIM;
    for (int k = tid; k < HDIM; k += 128) xs[k] = xr[k];
    __syncthreads();

    const int e = tid >> 2, l4 = tid & 3;
    float s = 0.f;
    for (int k = l4; k < HDIM; k += 4) s += xs[k] * gate_w[k * NEXP + e];
    s += __shfl_xor_sync(0xffffffffu, s, 1);
    s += __shfl_xor_sync(0xffffffffu, s, 2);
    if (l4 == 0) ls[e] = s;

    float g = 0.f;
    for (int k = tid; k < HDIM; k += 128) g += xs[k] * wsg[k];
    for (int o = 16; o; o >>= 1) g += __shfl_xor_sync(0xffffffffu, g, o);
    if ((tid & 31) == 0) gred[tid >> 5] = g;
    __syncthreads();

    if (tid < NEXP) logits_out[t * NEXP + tid] = ls[tid];
    if (tid == 0) {
        float gt = gred[0] + gred[1] + gred[2] + gred[3];
        g_sgate[t] = 1.f / (1.f + expf(-gt));
        float mx = -1e30f;
        for (int i = 0; i < NEXP; i++) mx = fmaxf(mx, ls[i]);
        float sum = 0.f;
        for (int i = 0; i < NEXP; i++) { float p = expf(ls[i] - mx); ps[i] = p; sum += p; }
        const float inv = 1.f / sum;
        for (int k = 0; k < TOPK; k++) {
            int best = 0; float bv = -1.f;
            for (int i = 0; i < NEXP; i++) if (ps[i] > bv) { bv = ps[i]; best = i; }
            g_top_e[t * TOPK + k] = best;
            g_top_w[t * TOPK + k] = bv * inv;
            ps[best] = -2.f;
        }
    }
}

__global__ void dispatch_kernel() {
    const int i = blockIdx.x * blockDim.x + threadIdx.x;
    if (i >= T_TOK * TOPK) return;
    const int e = g_top_e[i];
    const int pos = atomicAdd(&g_counts[e], 1);
    if (pos < CAP) {
        g_slot_tok[e * CAP + pos] = i >> 2;
        g_slot_w[e * CAP + pos]   = g_top_w[i];
    }
}

// ---------------- tf32 mma GEMM core -----------------------------------------
// ldmatrix-A (cvt-free), 1x8 warp grid: each warp owns all 128 M-rows and a
// private N-slice -> B fragments loaded exactly once per CTA.
#define BM 128
#define BK 32
#define NSTAGE 3

// MODE 0: dual-B, epilogue rtf(silu(g)*u) -> C           (expert & shared ph.1)
// MODE 1: single-B, epilogue w_slot * acc red.v2 -> out  (expert down-proj)
// MODE 2: single-B, epilogue sgate * acc -> C            (shared down, inits out)
template<int MODE>
__global__ __launch_bounds__(256, 2) void moe_gemm(
    const float* __restrict__ A0, int lda, int Ktot,
    const float* __restrict__ B1g, const float* __restrict__ B2g, int ldb,
    float* __restrict__ C0, int ldc,
    const int* __restrict__ gather,
    const int* __restrict__ cntp, int fixedCount,
    float* __restrict__ outp,
    long strideA, long strideB, long strideC)
{
    constexpr bool DUAL = (MODE == 0);
    constexpr int BN = DUAL ? 64 : 128;
    constexpr int WN = BN / 8;         // 8 warps across N
    constexpr int NI = WN / 8;         // 1 (MODE0) / 2 (MODE1,2)
    constexpr int MI = 8;              // each warp covers all 128 rows
    constexpr int TA = BM * BK;        // 4096 floats
    constexpr int TB = BK * BN;
    constexpr int GMASK = BN / 4 - 1;

    extern __shared__ float sm[];
    float* As  = sm;
    float* Bs  = As + NSTAGE * TA;
    float* B2s = Bs + NSTAGE * TB;
    __shared__ int rIdx[BM];

    const int e = blockIdx.z;
    const int count = cntp ? min(cntp[e], CAP) : fixedCount;
    const int m0 = blockIdx.y * BM;
    if (m0 >= count) return;
    const int n0 = blockIdx.x * BN;
    const int tid = threadIdx.x;

    const float* A  = A0 + (size_t)e * strideA;
    const float* B1 = B1g + (size_t)e * strideB;
    const float* B2 = DUAL ? (B2g + (size_t)e * strideB) : B1g;

    if (tid < BM) {
        const int mg = m0 + tid;
        int r = -1;
        if (mg < count) r = gather ? gather[e * CAP + mg] : mg;
        rIdx[tid] = r;
    }
    __syncthreads();

    auto loadA = [&](int buf, int kt) {
        const int k0 = kt * BK;
        #pragma unroll
        for (int i = 0; i < 4; i++) {
            const int li = tid + i * 256;
            const int m = li >> 3, k4 = li & 7;
            const int grp = k4 ^ (m & 7);
            float* dst = As + buf * TA + m * BK + grp * 4;
            const int r = rIdx[m];
            const float* src = A + (size_t)max(r, 0) * lda + k0 + k4 * 4;
            cp16(dst, src, r >= 0);
        }
    };
    auto loadB = [&](const float* Bg, float* Bsb, int buf, int kt) {
        const int k0 = kt * BK;
        #pragma unroll
        for (int i = 0; i < TB / 1024; i++) {
            const int li = tid + i * 256;
            const int k = li / (BN / 4), n4 = li % (BN / 4);
            const int grp = (n4 ^ ((k & 3) << 1)) & GMASK;
            float* dst = Bsb + buf * TB + k * BN + grp * 4;
            const float* src = Bg + (size_t)(k0 + k) * ldb + n0 + n4 * 4;
            cp16(dst, src, true);
        }
    };

    const int warp = tid >> 5, lane = tid & 31;
    const int wn = warp;                       // 1 x 8 warp grid (N only)
    const int lr = lane >> 2, lc = lane & 3;
    const int lrow = lane & 7, lmat = lane >> 3;

    uint32_t arow[MI];
    #pragma unroll
    for (int mi = 0; mi < MI; mi++)
        arow[mi] = (uint32_t)(mi * 16 + (lmat & 1) * 8 + lrow) * (BK * 4);
    const uint32_t AsU = (uint32_t)__cvta_generic_to_shared(As);

    int boff[NI];
    #pragma unroll
    for (int ni = 0; ni < NI; ni++) {
        const int n = wn * WN + ni * 8 + lr;
        const int g = ((n >> 2) ^ (lc << 1)) & GMASK;
        boff[ni] = g * 4 + (n & 3);
    }

    float acc[MI][NI][4];
    float acc2[MI][NI][4];
    #pragma unroll
    for (int mi = 0; mi < MI; mi++)
        #pragma unroll
        for (int ni = 0; ni < NI; ni++)
            #pragma unroll
            for (int q = 0; q < 4; q++) {
                acc[mi][ni][q] = 0.f;
                if constexpr (DUAL) acc2[mi][ni][q] = 0.f;
            }

    const int nK = Ktot / BK;

    #pragma unroll
    for (int p = 0; p < NSTAGE - 1; p++) {
        if (p < nK) {
            loadA(p, p); loadB(B1, Bs, p, p);
            if constexpr (DUAL) loadB(B2, B2s, p, p);
        }
        asm volatile("cp.async.commit_group;\n");
    }

    for (int kt = 0; kt < nK; kt++) {
        asm volatile("cp.async.wait_group %0;\n" :: "n"(NSTAGE - 2));
        __syncthreads();
        const int ldst = kt + NSTAGE - 1;
        if (ldst < nK) {
            const int lb = ldst % NSTAGE;
            loadA(lb, ldst); loadB(B1, Bs, lb, ldst);
            if constexpr (DUAL) loadB(B2, B2s, lb, ldst);
        }
        asm volatile("cp.async.commit_group;\n");

        const int buf = kt % NSTAGE;
        const uint32_t AbU = AsU + buf * TA * 4;
        const float* Bb  = Bs + buf * TB;
        const float* B2b = B2s + buf * TB;
        #pragma unroll
        for (int s = 0; s < 4; s++) {
            const uint32_t gsel = (uint32_t)((2 * s + (lmat >> 1)) ^ lrow);
            const int kr = s * 8 + lc;
            // B fragments for this k-slice (4 live regs in MODE0)
            uint32_t bf[NI][2], cf[DUAL ? NI : 1][2];
            #pragma unroll
            for (int ni = 0; ni < NI; ni++) {
                bf[ni][0] = f2tf(Bb[kr * BN + boff[ni]]);
                bf[ni][1] = f2tf(Bb[(kr + 4) * BN + boff[ni]]);
                if constexpr (DUAL) {
                    cf[ni][0] = f2tf(B2b[kr * BN + boff[ni]]);
                    cf[ni][1] = f2tf(B2b[(kr + 4) * BN + boff[ni]]);
                }
            }
            // sweep the 8 M fragments with short-lived A fragments
            #pragma unroll
            for (int mi = 0; mi < MI; mi++) {
                uint32_t a0, a1, a2, a3;
                LDSM4(a0, a1, a2, a3, AbU + arow[mi] + gsel * 16u);
                #pragma unroll
                for (int ni = 0; ni < NI; ni++) {
                    mma_m16n8k8(acc[mi][ni], a0, a1, a2, a3, bf[ni][0], bf[ni][1]);
                    if constexpr (DUAL)
                        mma_m16n8k8(acc2[mi][ni], a0, a1, a2, a3, cf[ni][0], cf[ni][1]);
                }
            }
        }
    }

    // epilogue
    #pragma unroll
    for (int mi = 0; mi < MI; mi++) {
        const int rbase = mi * 16 + lr;
        #pragma unroll
        for (int half = 0; half < 2; half++) {
            const int r = rbase + half * 8;
            const int mg = m0 + r;
            const bool valid = (mg < count);
            #pragma unroll
            for (int ni = 0; ni < NI; ni++) {
                const int n = n0 + wn * WN + ni * 8 + lc * 2;
                const float c0 = acc[mi][ni][half * 2 + 0];
                const float c1 = acc[mi][ni][half * 2 + 1];
                if constexpr (MODE == 0) {
                    if (valid) {
                        const float u0 = acc2[mi][ni][half * 2 + 0];
                        const float u1 = acc2[mi][ni][half * 2 + 1];
                        const float h0 = rtf((c0 / (1.f + __expf(-c0))) * u0);
                        const float h1 = rtf((c1 / (1.f + __expf(-c1))) * u1);
                        float* dst = C0 + (size_t)e * strideC + (size_t)mg * ldc + n;
                        *reinterpret_cast<float2*>(dst) = make_float2(h0, h1);
                    }
                } else if constexpr (MODE == 1) {
                    if (valid) {
                        const int tok = g_slot_tok[e * CAP + mg];
                        const float w = g_slot_w[e * CAP + mg];
                        float* dst = outp + (size_t)tok * HDIM + n;
                        asm volatile("red.global.add.v2.f32 [%0], {%1, %2};"
                                     :: "l"(dst), "f"(w * c0), "f"(w * c1) : "memory");
                    }
                } else {
                    const float sg = g_sgate[mg];
                    float* dst = C0 + (size_t)mg * ldc + n;
                    *reinterpret_cast<float2*>(dst) = make_float2(sg * c0, sg * c1);
                }
            }
        }
    }
}

// ---------------- launcher ---------------------------------------------------
extern "C" void kernel_launch(void* const* d_in, const int* in_sizes, int n_in,
                              void* d_out, int out_size)
{
    const float* x       = (const float*)d_in[0];
    const float* gate_w  = (const float*)d_in[1];
    const float* w_gate  = (const float*)d_in[2];
    const float* w_up    = (const float*)d_in[3];
    const float* w_down  = (const float*)d_in[4];
    const float* ws_gate = (const float*)d_in[5];
    const float* ws_up   = (const float*)d_in[6];
    const float* ws_down = (const float*)d_in[7];
    const float* w_sg    = (const float*)d_in[8];
    float* out    = (float*)d_out;
    float* logits = out + (size_t)T_TOK * HDIM;

    const int SMEM  = NSTAGE * (BM * BK + 2 * BK * 64) * 4;   // MODE0: 96KB
    const int SMEM2 = NSTAGE * (BM * BK + BK * 128) * 4;      // MODE1/2: 96KB
    cudaFuncSetAttribute((const void*)moe_gemm<0>, cudaFuncAttributeMaxDynamicSharedMemorySize, SMEM);
    cudaFuncSetAttribute((const void*)moe_gemm<1>, cudaFuncAttributeMaxDynamicSharedMemorySize, SMEM2);
    cudaFuncSetAttribute((const void*)moe_gemm<2>, cudaFuncAttributeMaxDynamicSharedMemorySize, SMEM2);

    float* h;  cudaGetSymbolAddress((void**)&h,  g_h);
    float* hs; cudaGetSymbolAddress((void**)&hs, g_hs);
    float* xr; cudaGetSymbolAddress((void**)&xr, g_xr);
    int* counts; cudaGetSymbolAddress((void**)&counts, g_counts);
    int* slots;  cudaGetSymbolAddress((void**)&slots,  g_slot_tok);

    zero_counts_kernel<<<1, 32>>>();
    round_x_kernel<<<(T_TOK * HDIM / 4) / 256, 256>>>(x);
    router_kernel<<<T_TOK, 128>>>(x, gate_w, w_sg, logits);
    dispatch_kernel<<<(T_TOK * TOPK + 255) / 256, 256>>>();

    // expert phase 1: h = rtf(silu(xg@Wg) * (xg@Wu))
    moe_gemm<0><<<dim3(IDIM / 64, 2, NEXP), 256, SMEM>>>(
        xr, HDIM, HDIM, w_gate, w_up, IDIM, h, IDIM,
        slots, counts, 0, nullptr,
        0L, (long)HDIM * IDIM, (long)CAP * IDIM);

    // shared phase 1: hs = rtf(silu(x@Wsg) * (x@Wsu))
    moe_gemm<0><<<dim3(ISH / 64, T_TOK / BM, 1), 256, SMEM>>>(
        xr, HDIM, HDIM, ws_gate, ws_up, ISH, hs, ISH,
        nullptr, nullptr, T_TOK, nullptr, 0L, 0L, 0L);

    // shared phase 2: out = sgate * (hs@Wsd)   (initializes out)
    moe_gemm<2><<<dim3(HDIM / 128, T_TOK / BM, 1), 256, SMEM2>>>(
        hs, ISH, ISH, ws_down, nullptr, HDIM, out, HDIM,
        nullptr, nullptr, T_TOK, nullptr, 0L, 0L, 0L);

    // expert phase 2: out[tok] += w_slot * (h@Wd)
    moe_gemm<1><<<dim3(HDIM / 128, 2, NEXP), 256, SMEM2>>>(
        h, IDIM, IDIM, w_down, nullptr, HDIM, nullptr, 0,
        nullptr, counts, 0, out,
        (long)CAP * IDIM, (long)IDIM * HDIM, 0L);
}

// round 11
// speedup vs baseline: 1.1855x; 1.1855x over previous
#include <cuda_runtime.h>
#include <cuda_fp16.h>
#include <cstdint>
#include <math.h>

#define T_TOK 1024
#define HDIM  2048
#define NEXP  32
#define IDIM  1408
#define ISH   5632
#define TOPK  4
#define CAP   256

__device__ int    g_counts[NEXP];
__device__ int    g_top_e[T_TOK*TOPK];
__device__ float  g_top_w[T_TOK*TOPK];
__device__ int    g_slot_tok[NEXP*CAP];
__device__ float  g_slot_w[NEXP*CAP];
__device__ float  g_sgate[T_TOK];
// fp16 scratch
__device__ __half g_x16[(size_t)T_TOK*HDIM];
__device__ __half g_wg16[(size_t)NEXP*HDIM*IDIM];
__device__ __half g_wu16[(size_t)NEXP*HDIM*IDIM];
__device__ __half g_wd16[(size_t)NEXP*IDIM*HDIM];
__device__ __half g_wsg16[(size_t)HDIM*ISH];
__device__ __half g_wsu16[(size_t)HDIM*ISH];
__device__ __half g_wsd16[(size_t)ISH*HDIM];
__device__ __half g_h16[(size_t)NEXP*CAP*IDIM];
__device__ __half g_hs16[(size_t)T_TOK*ISH];

// ---------------- helpers ----------------------------------------------------
__device__ __forceinline__ void mma_f16(float c[4],
    uint32_t a0, uint32_t a1, uint32_t a2, uint32_t a3, uint32_t b0, uint32_t b1)
{
    asm volatile(
      "mma.sync.aligned.m16n8k16.row.col.f32.f16.f16.f32 "
      "{%0,%1,%2,%3},{%4,%5,%6,%7},{%8,%9},{%0,%1,%2,%3};\n"
      : "+f"(c[0]), "+f"(c[1]), "+f"(c[2]), "+f"(c[3])
      : "r"(a0), "r"(a1), "r"(a2), "r"(a3), "r"(b0), "r"(b1));
}
__device__ __forceinline__ void cp16(void* sdst, const void* gsrc, bool pred) {
    uint32_t s = (uint32_t)__cvta_generic_to_shared(sdst);
    int sz = pred ? 16 : 0;
    asm volatile("cp.async.cg.shared.global [%0], [%1], 16, %2;\n"
                 :: "r"(s), "l"(gsrc), "r"(sz));
}
#define LDSM4(r0,r1,r2,r3,a) \
    asm volatile("ldmatrix.sync.aligned.m8n8.x4.shared.b16 {%0,%1,%2,%3}, [%4];" \
        : "=r"(r0), "=r"(r1), "=r"(r2), "=r"(r3) : "r"(a))
#define LDSMT2(r0,r1,a) \
    asm volatile("ldmatrix.sync.aligned.m8n8.x2.trans.shared.b16 {%0,%1}, [%2];" \
        : "=r"(r0), "=r"(r1) : "r"(a))
#define LDSMT4(r0,r1,r2,r3,a) \
    asm volatile("ldmatrix.sync.aligned.m8n8.x4.trans.shared.b16 {%0,%1,%2,%3}, [%4];" \
        : "=r"(r0), "=r"(r1), "=r"(r2), "=r"(r3) : "r"(a))

// ---------------- small kernels ----------------------------------------------
__global__ void zero_counts_kernel() {
    if (threadIdx.x < NEXP) g_counts[threadIdx.x] = 0;
}

__global__ __launch_bounds__(256) void cvt16_kernel(
    const float4* __restrict__ src, __half2* __restrict__ dst, int n4)
{
    const int i = blockIdx.x * 256 + threadIdx.x;
    if (i >= n4) return;
    float4 v = src[i];
    dst[2 * i]     = __floats2half2_rn(v.x, v.y);
    dst[2 * i + 1] = __floats2half2_rn(v.z, v.w);
}

__global__ __launch_bounds__(128) void router_kernel(
    const float* __restrict__ x, const float* __restrict__ gate_w,
    const float* __restrict__ wsg, float* __restrict__ logits_out)
{
    __shared__ float xs[HDIM];
    __shared__ float ls[NEXP];
    __shared__ float ps[NEXP];
    __shared__ float gred[4];
    const int t = blockIdx.x;
    const int tid = threadIdx.x;
    const float* xr = x + (size_t)t * HDIM;
    for (int k = tid; k < HDIM; k += 128) xs[k] = xr[k];
    __syncthreads();

    const int e = tid >> 2, l4 = tid & 3;
    float s = 0.f;
    for (int k = l4; k < HDIM; k += 4) s += xs[k] * gate_w[k * NEXP + e];
    s += __shfl_xor_sync(0xffffffffu, s, 1);
    s += __shfl_xor_sync(0xffffffffu, s, 2);
    if (l4 == 0) ls[e] = s;

    float g = 0.f;
    for (int k = tid; k < HDIM; k += 128) g += xs[k] * wsg[k];
    for (int o = 16; o; o >>= 1) g += __shfl_xor_sync(0xffffffffu, g, o);
    if ((tid & 31) == 0) gred[tid >> 5] = g;
    __syncthreads();

    if (tid < NEXP) logits_out[t * NEXP + tid] = ls[tid];
    if (tid == 0) {
        float gt = gred[0] + gred[1] + gred[2] + gred[3];
        g_sgate[t] = 1.f / (1.f + expf(-gt));
        float mx = -1e30f;
        for (int i = 0; i < NEXP; i++) mx = fmaxf(mx, ls[i]);
        float sum = 0.f;
        for (int i = 0; i < NEXP; i++) { float p = expf(ls[i] - mx); ps[i] = p; sum += p; }
        const float inv = 1.f / sum;
        for (int k = 0; k < TOPK; k++) {
            int best = 0; float bv = -1.f;
            for (int i = 0; i < NEXP; i++) if (ps[i] > bv) { bv = ps[i]; best = i; }
            g_top_e[t * TOPK + k] = best;
            g_top_w[t * TOPK + k] = bv * inv;
            ps[best] = -2.f;
        }
    }
}

__global__ void dispatch_kernel() {
    const int i = blockIdx.x * blockDim.x + threadIdx.x;
    if (i >= T_TOK * TOPK) return;
    const int e = g_top_e[i];
    const int pos = atomicAdd(&g_counts[e], 1);
    if (pos < CAP) {
        g_slot_tok[e * CAP + pos] = i >> 2;
        g_slot_w[e * CAP + pos]   = g_top_w[i];
    }
}

// ---------------- fp16 mma GEMM core -----------------------------------------
// A fp16 K-major (128B rows, xor-swizzled), B fp16 K-major + ldmatrix.trans.
// 1x8 warp grid: each warp owns all 128 M rows and a private N slice.
#define BM 128
#define BK 64
#define NSTAGE 3

// MODE 0: dual-B (BN=64), epilogue fp16(silu(g)*u) -> C16   (expert & shared ph.1)
// MODE 1: single-B (BN=128), epilogue w_slot * acc red.v2   (expert down-proj)
// MODE 2: single-B (BN=128), epilogue sgate * acc -> Cf32   (shared down, inits out)
template<int MODE>
__global__ __launch_bounds__(256, 2) void moe_gemm(
    const __half* __restrict__ A0, int lda, int Ktot,
    const __half* __restrict__ B1g, const __half* __restrict__ B2g, int ldb,
    void* __restrict__ C0, int ldc,
    const int* __restrict__ gather,
    const int* __restrict__ cntp, int fixedCount,
    float* __restrict__ outp,
    long strideA, long strideB, long strideC)
{
    constexpr bool DUAL = (MODE == 0);
    constexpr int BN  = DUAL ? 64 : 128;
    constexpr int WN  = BN / 8;          // 8 warps across N
    constexpr int NI  = WN / 8;          // 1 (MODE0) / 2 (MODE1,2)
    constexpr int MI  = 8;               // all 128 rows per warp
    constexpr int TAH = BM * BK;         // halves per A stage (8192)
    constexpr int TBH = BK * BN;         // halves per B stage
    constexpr int CPB = BN / 8;          // 16B chunks per B row

    extern __shared__ __align__(16) char smz[];
    __half* As  = (__half*)smz;
    __half* Bs  = As + NSTAGE * TAH;
    __half* B2s = Bs + NSTAGE * TBH;
    __shared__ int rIdx[BM];

    const int e = blockIdx.z;
    const int count = cntp ? min(cntp[e], CAP) : fixedCount;
    const int m0 = blockIdx.y * BM;
    if (m0 >= count) return;
    const int n0 = blockIdx.x * BN;
    const int tid = threadIdx.x;

    const __half* A  = A0 + (size_t)e * strideA;
    const __half* B1 = B1g + (size_t)e * strideB;
    const __half* B2 = DUAL ? (B2g + (size_t)e * strideB) : B1g;

    if (tid < BM) {
        const int mg = m0 + tid;
        int r = -1;
        if (mg < count) r = gather ? gather[e * CAP + mg] : mg;
        rIdx[tid] = r;
    }
    __syncthreads();

    auto loadA = [&](int buf, int kt) {
        const int k0 = kt * BK;
        #pragma unroll
        for (int i = 0; i < 4; i++) {
            const int li = tid + i * 256;
            const int m = li >> 3, kg = li & 7;
            __half* dst = As + buf * TAH + m * BK + ((kg ^ (m & 7)) << 3);
            const int r = rIdx[m];
            const __half* src = A + (size_t)max(r, 0) * lda + k0 + kg * 8;
            cp16(dst, src, r >= 0);
        }
    };
    auto loadB = [&](const __half* Bg, __half* Bsb, int buf, int kt) {
        const int k0 = kt * BK;
        #pragma unroll
        for (int i = 0; i < CPB / 4; i++) {
            const int li = tid + i * 256;
            const int k = li / CPB, gc = li % CPB;
            __half* dst = Bsb + buf * TBH + k * BN + ((gc ^ (k & 7)) << 3);
            const __half* src = Bg + (size_t)(k0 + k) * ldb + n0 + gc * 8;
            cp16(dst, src, true);
        }
    };

    const int warp = tid >> 5, lane = tid & 31;
    const int wn = warp;
    const int lr = lane >> 2, lc = lane & 3;
    const int lrow = lane & 7, lmat = lane >> 3;

    uint32_t arow[MI];
    #pragma unroll
    for (int mi = 0; mi < MI; mi++)
        arow[mi] = (uint32_t)(mi * 16 + (lmat & 1) * 8 + lrow) * (BK * 2);
    const uint32_t AsU = (uint32_t)__cvta_generic_to_shared(As);
    const uint32_t BsU = (uint32_t)__cvta_generic_to_shared(Bs);
    const uint32_t B2U = (uint32_t)__cvta_generic_to_shared(B2s);

    float acc[MI][NI][4];
    float acc2[MI][NI][4];
    #pragma unroll
    for (int mi = 0; mi < MI; mi++)
        #pragma unroll
        for (int ni = 0; ni < NI; ni++)
            #pragma unroll
            for (int q = 0; q < 4; q++) {
                acc[mi][ni][q] = 0.f;
                if constexpr (DUAL) acc2[mi][ni][q] = 0.f;
            }

    const int nK = Ktot / BK;

    #pragma unroll
    for (int p = 0; p < NSTAGE - 1; p++) {
        if (p < nK) {
            loadA(p, p); loadB(B1, Bs, p, p);
            if constexpr (DUAL) loadB(B2, B2s, p, p);
        }
        asm volatile("cp.async.commit_group;\n");
    }

    for (int kt = 0; kt < nK; kt++) {
        asm volatile("cp.async.wait_group %0;\n" :: "n"(NSTAGE - 2));
        __syncthreads();
        const int ldst = kt + NSTAGE - 1;
        if (ldst < nK) {
            const int lb = ldst % NSTAGE;
            loadA(lb, ldst); loadB(B1, Bs, lb, ldst);
            if constexpr (DUAL) loadB(B2, B2s, lb, ldst);
        }
        asm volatile("cp.async.commit_group;\n");

        const int buf = kt % NSTAGE;
        const uint32_t AbU  = AsU + buf * TAH * 2;
        const uint32_t B1bU = BsU + buf * TBH * 2;
        const uint32_t B2bU = B2U + buf * TBH * 2;

        #pragma unroll
        for (int s = 0; s < 4; s++) {            // four k16 slices per BK=64
            const int krow = s * 16 + (lane & 15);
            uint32_t bf[NI][2], cf[DUAL ? NI : 1][2];
            if constexpr (DUAL) {
                const uint32_t ba = (uint32_t)(krow * (BN * 2) + ((wn ^ (krow & 7)) << 4));
                LDSMT2(bf[0][0], bf[0][1], B1bU + ba);
                LDSMT2(cf[0][0], cf[0][1], B2bU + ba);
            } else {
                const int gn = wn * 2 + (lane >> 4);
                const uint32_t ba = (uint32_t)(krow * (BN * 2) + ((gn ^ (krow & 7)) << 4));
                LDSMT4(bf[0][0], bf[0][1], bf[1][0], bf[1][1], B1bU + ba);
            }
            const uint32_t gsel = (uint32_t)((2 * s + (lmat >> 1)) ^ lrow);
            #pragma unroll
            for (int mi = 0; mi < MI; mi++) {
                uint32_t a0, a1, a2, a3;
                LDSM4(a0, a1, a2, a3, AbU + arow[mi] + gsel * 16u);
                #pragma unroll
                for (int ni = 0; ni < NI; ni++) {
                    mma_f16(acc[mi][ni], a0, a1, a2, a3, bf[ni][0], bf[ni][1]);
                    if constexpr (DUAL)
                        mma_f16(acc2[mi][ni], a0, a1, a2, a3, cf[ni][0], cf[ni][1]);
                }
            }
        }
    }

    // epilogue
    #pragma unroll
    for (int mi = 0; mi < MI; mi++) {
        const int rbase = mi * 16 + lr;
        #pragma unroll
        for (int half = 0; half < 2; half++) {
            const int r = rbase + half * 8;
            const int mg = m0 + r;
            const bool valid = (mg < count);
            #pragma unroll
            for (int ni = 0; ni < NI; ni++) {
                const int n = n0 + wn * WN + ni * 8 + lc * 2;
                const float c0 = acc[mi][ni][half * 2 + 0];
                const float c1 = acc[mi][ni][half * 2 + 1];
                if constexpr (MODE == 0) {
                    if (valid) {
                        const float u0 = acc2[mi][ni][half * 2 + 0];
                        const float u1 = acc2[mi][ni][half * 2 + 1];
                        const float h0 = (c0 / (1.f + __expf(-c0))) * u0;
                        const float h1 = (c1 / (1.f + __expf(-c1))) * u1;
                        __half* dst = (__half*)C0 + (size_t)e * strideC + (size_t)mg * ldc + n;
                        *reinterpret_cast<__half2*>(dst) = __floats2half2_rn(h0, h1);
                    }
                } else if constexpr (MODE == 1) {
                    if (valid) {
                        const int tok = g_slot_tok[e * CAP + mg];
                        const float w = g_slot_w[e * CAP + mg];
                        float* dst = outp + (size_t)tok * HDIM + n;
                        asm volatile("red.global.add.v2.f32 [%0], {%1, %2};"
                                     :: "l"(dst), "f"(w * c0), "f"(w * c1) : "memory");
                    }
                } else {
                    const float sg = g_sgate[mg];
                    float* dst = (float*)C0 + (size_t)mg * ldc + n;
                    *reinterpret_cast<float2*>(dst) = make_float2(sg * c0, sg * c1);
                }
            }
        }
    }
}

// ---------------- launcher ---------------------------------------------------
static void cvt16(const float* src, __half* dst, size_t n) {
    const int n4 = (int)(n / 4);
    cvt16_kernel<<<(n4 + 255) / 256, 256>>>(
        (const float4*)src, (__half2*)dst, n4);
}

extern "C" void kernel_launch(void* const* d_in, const int* in_sizes, int n_in,
                              void* d_out, int out_size)
{
    const float* x       = (const float*)d_in[0];
    const float* gate_w  = (const float*)d_in[1];
    const float* w_gate  = (const float*)d_in[2];
    const float* w_up    = (const float*)d_in[3];
    const float* w_down  = (const float*)d_in[4];
    const float* ws_gate = (const float*)d_in[5];
    const float* ws_up   = (const float*)d_in[6];
    const float* ws_down = (const float*)d_in[7];
    const float* w_sg    = (const float*)d_in[8];
    float* out    = (float*)d_out;
    float* logits = out + (size_t)T_TOK * HDIM;

    const int SMEM  = NSTAGE * (BM * BK + 2 * BK * 64) * 2;   // MODE0: 96KB
    const int SMEM2 = NSTAGE * (BM * BK + BK * 128) * 2;      // MODE1/2: 96KB
    cudaFuncSetAttribute((const void*)moe_gemm<0>, cudaFuncAttributeMaxDynamicSharedMemorySize, SMEM);
    cudaFuncSetAttribute((const void*)moe_gemm<1>, cudaFuncAttributeMaxDynamicSharedMemorySize, SMEM2);
    cudaFuncSetAttribute((const void*)moe_gemm<2>, cudaFuncAttributeMaxDynamicSharedMemorySize, SMEM2);

    __half *x16, *wg16, *wu16, *wd16, *wsg16, *wsu16, *wsd16, *h16, *hs16;
    cudaGetSymbolAddress((void**)&x16,  g_x16);
    cudaGetSymbolAddress((void**)&wg16, g_wg16);
    cudaGetSymbolAddress((void**)&wu16, g_wu16);
    cudaGetSymbolAddress((void**)&wd16, g_wd16);
    cudaGetSymbolAddress((void**)&wsg16, g_wsg16);
    cudaGetSymbolAddress((void**)&wsu16, g_wsu16);
    cudaGetSymbolAddress((void**)&wsd16, g_wsd16);
    cudaGetSymbolAddress((void**)&h16,  g_h16);
    cudaGetSymbolAddress((void**)&hs16, g_hs16);
    int* counts; cudaGetSymbolAddress((void**)&counts, g_counts);
    int* slots;  cudaGetSymbolAddress((void**)&slots,  g_slot_tok);

    zero_counts_kernel<<<1, 32>>>();
    router_kernel<<<T_TOK, 128>>>(x, gate_w, w_sg, logits);
    dispatch_kernel<<<(T_TOK * TOPK + 255) / 256, 256>>>();

    // fp16 conversions (streaming, ~1.9GB traffic)
    cvt16(x,       x16,  (size_t)T_TOK * HDIM);
    cvt16(w_gate,  wg16, (size_t)NEXP * HDIM * IDIM);
    cvt16(w_up,    wu16, (size_t)NEXP * HDIM * IDIM);
    cvt16(w_down,  wd16, (size_t)NEXP * IDIM * HDIM);
    cvt16(ws_gate, wsg16, (size_t)HDIM * ISH);
    cvt16(ws_up,   wsu16, (size_t)HDIM * ISH);
    cvt16(ws_down, wsd16, (size_t)ISH * HDIM);

    // expert phase 1: h16 = fp16(silu(xg@Wg) * (xg@Wu))
    moe_gemm<0><<<dim3(IDIM / 64, 2, NEXP), 256, SMEM>>>(
        x16, HDIM, HDIM, wg16, wu16, IDIM, h16, IDIM,
        slots, counts, 0, nullptr,
        0L, (long)HDIM * IDIM, (long)CAP * IDIM);

    // shared phase 1: hs16 = fp16(silu(x@Wsg) * (x@Wsu))
    moe_gemm<0><<<dim3(ISH / 64, T_TOK / BM, 1), 256, SMEM>>>(
        x16, HDIM, HDIM, wsg16, wsu16, ISH, hs16, ISH,
        nullptr, nullptr, T_TOK, nullptr, 0L, 0L, 0L);

    // shared phase 2: out = sgate * (hs@Wsd)   (initializes out)
    moe_gemm<2><<<dim3(HDIM / 128, T_TOK / BM, 1), 256, SMEM2>>>(
        hs16, ISH, ISH, wsd16, nullptr, HDIM, out, HDIM,
        nullptr, nullptr, T_TOK, nullptr, 0L, 0L, 0L);

    // expert phase 2: out[tok] += w_slot * (h@Wd)
    moe_gemm<1><<<dim3(HDIM / 128, 2, NEXP), 256, SMEM2>>>(
        h16, IDIM, IDIM, wd16, nullptr, HDIM, nullptr, 0,
        nullptr, counts, 0, out,
        (long)CAP * IDIM, (long)IDIM * HDIM, 0L);
}

// round 14
// speedup vs baseline: 1.5286x; 1.2894x over previous
#include <cuda_runtime.h>
#include <cuda_fp16.h>
#include <cstdint>
#include <math.h>

#define T_TOK 1024
#define HDIM  2048
#define NEXP  32
#define IDIM  1408
#define ISH   5632
#define TOPK  4
#define CAP   256

__device__ int    g_counts[NEXP];
__device__ int    g_top_e[T_TOK*TOPK];
__device__ float  g_top_w[T_TOK*TOPK];
__device__ int    g_slot_tok[NEXP*CAP];
__device__ float  g_slot_w[NEXP*CAP];
__device__ float  g_sgate[T_TOK];
// fp16 scratch
__device__ __half g_x16[(size_t)T_TOK*HDIM];
__device__ __half g_wg16[(size_t)NEXP*HDIM*IDIM];
__device__ __half g_wu16[(size_t)NEXP*HDIM*IDIM];
__device__ __half g_wd16[(size_t)NEXP*IDIM*HDIM];
__device__ __half g_wsg16[(size_t)HDIM*ISH];
__device__ __half g_wsu16[(size_t)HDIM*ISH];
__device__ __half g_wsd16[(size_t)ISH*HDIM];
__device__ __half g_h16[(size_t)NEXP*CAP*IDIM];
__device__ __half g_hs16[(size_t)T_TOK*ISH];

// ---------------- helpers ----------------------------------------------------
__device__ __forceinline__ void mma_f16(float c[4],
    uint32_t a0, uint32_t a1, uint32_t a2, uint32_t a3, uint32_t b0, uint32_t b1)
{
    asm volatile(
      "mma.sync.aligned.m16n8k16.row.col.f32.f16.f16.f32 "
      "{%0,%1,%2,%3},{%4,%5,%6,%7},{%8,%9},{%0,%1,%2,%3};\n"
      : "+f"(c[0]), "+f"(c[1]), "+f"(c[2]), "+f"(c[3])
      : "r"(a0), "r"(a1), "r"(a2), "r"(a3), "r"(b0), "r"(b1));
}
__device__ __forceinline__ void cp16(void* sdst, const void* gsrc, bool pred) {
    uint32_t s = (uint32_t)__cvta_generic_to_shared(sdst);
    int sz = pred ? 16 : 0;
    asm volatile("cp.async.cg.shared.global [%0], [%1], 16, %2;\n"
                 :: "r"(s), "l"(gsrc), "r"(sz));
}
// pack two floats into fp16x2 (low = a, high = b)
__device__ __forceinline__ uint32_t packh2(float a, float b) {
    uint32_t r;
    asm("cvt.rn.f16x2.f32 %0, %1, %2;" : "=r"(r) : "f"(b), "f"(a));
    return r;
}
#define LDSM4(r0,r1,r2,r3,a) \
    asm volatile("ldmatrix.sync.aligned.m8n8.x4.shared.b16 {%0,%1,%2,%3}, [%4];" \
        : "=r"(r0), "=r"(r1), "=r"(r2), "=r"(r3) : "r"(a))
#define LDSMT2(r0,r1,a) \
    asm volatile("ldmatrix.sync.aligned.m8n8.x2.trans.shared.b16 {%0,%1}, [%2];" \
        : "=r"(r0), "=r"(r1) : "r"(a))
#define LDSMT4(r0,r1,r2,r3,a) \
    asm volatile("ldmatrix.sync.aligned.m8n8.x4.trans.shared.b16 {%0,%1,%2,%3}, [%4];" \
        : "=r"(r0), "=r"(r1), "=r"(r2), "=r"(r3) : "r"(a))

// ---------------- small kernels ----------------------------------------------
__global__ void zero_counts_kernel() {
    if (threadIdx.x < NEXP) g_counts[threadIdx.x] = 0;
}

__global__ __launch_bounds__(256) void zero_out_kernel(float4* __restrict__ p, int n4) {
    const int i = blockIdx.x * 256 + threadIdx.x;
    if (i < n4) p[i] = make_float4(0.f, 0.f, 0.f, 0.f);
}

// 32B read / 16B write per thread
__global__ __launch_bounds__(256) void cvt16_kernel(
    const float4* __restrict__ src, uint4* __restrict__ dst, int n8)
{
    const int i = blockIdx.x * 256 + threadIdx.x;
    if (i >= n8) return;
    float4 a = src[2 * i], b = src[2 * i + 1];
    uint4 o;
    o.x = packh2(a.x, a.y);
    o.y = packh2(a.z, a.w);
    o.z = packh2(b.x, b.y);
    o.w = packh2(b.z, b.w);
    dst[i] = o;
}

__global__ __launch_bounds__(128) void router_kernel(
    const float* __restrict__ x, const float* __restrict__ gate_w,
    const float* __restrict__ wsg, float* __restrict__ logits_out)
{
    __shared__ float xs[HDIM];
    __shared__ float ls[NEXP];
    __shared__ float ps[NEXP];
    __shared__ float gred[4];
    const int t = blockIdx.x;
    const int tid = threadIdx.x;
    const float* xr = x + (size_t)t * HDIM;
    for (int k = tid; k < HDIM; k += 128) xs[k] = xr[k];
    __syncthreads();

    const int e = tid >> 2, l4 = tid & 3;
    float s = 0.f;
    for (int k = l4; k < HDIM; k += 4) s += xs[k] * gate_w[k * NEXP + e];
    s += __shfl_xor_sync(0xffffffffu, s, 1);
    s += __shfl_xor_sync(0xffffffffu, s, 2);
    if (l4 == 0) ls[e] = s;

    float g = 0.f;
    for (int k = tid; k < HDIM; k += 128) g += xs[k] * wsg[k];
    for (int o = 16; o; o >>= 1) g += __shfl_xor_sync(0xffffffffu, g, o);
    if ((tid & 31) == 0) gred[tid >> 5] = g;
    __syncthreads();

    if (tid < NEXP) logits_out[t * NEXP + tid] = ls[tid];
    if (tid == 0) {
        float gt = gred[0] + gred[1] + gred[2] + gred[3];
        g_sgate[t] = 1.f / (1.f + expf(-gt));
        float mx = -1e30f;
        for (int i = 0; i < NEXP; i++) mx = fmaxf(mx, ls[i]);
        float sum = 0.f;
        for (int i = 0; i < NEXP; i++) { float p = expf(ls[i] - mx); ps[i] = p; sum += p; }
        const float inv = 1.f / sum;
        for (int k = 0; k < TOPK; k++) {
            int best = 0; float bv = -1.f;
            for (int i = 0; i < NEXP; i++) if (ps[i] > bv) { bv = ps[i]; best = i; }
            g_top_e[t * TOPK + k] = best;
            g_top_w[t * TOPK + k] = bv * inv;
            ps[best] = -2.f;
        }
    }
}

__global__ void dispatch_kernel() {
    const int i = blockIdx.x * blockDim.x + threadIdx.x;
    if (i >= T_TOK * TOPK) return;
    const int e = g_top_e[i];
    const int pos = atomicAdd(&g_counts[e], 1);
    if (pos < CAP) {
        g_slot_tok[e * CAP + pos] = i >> 2;
        g_slot_w[e * CAP + pos]   = g_top_w[i];
    }
}

// ---------------- fp16 mma GEMM core -----------------------------------------
#define BM 128
#define BK 64
#define NSTAGE 3

// MODE 0: dual-B (BN=64), epilogue fp16(silu(g)*u) -> C16   (expert & shared ph.1)
// MODE 1: single-B (BN=128), epilogue w_slot * acc red.v2   (expert down-proj)
// MODE 2: single-B (BN=128), epilogue sgate * acc red.v2    (shared down-proj)
template<int MODE>
__global__ __launch_bounds__(256, 2) void moe_gemm(
    const __half* __restrict__ A0, int lda, int Ktot,
    const __half* __restrict__ B1g, const __half* __restrict__ B2g, int ldb,
    void* __restrict__ C0, int ldc,
    const int* __restrict__ gather,
    const int* __restrict__ cntp, int fixedCount,
    float* __restrict__ outp,
    long strideA, long strideB, long strideC)
{
    constexpr bool DUAL = (MODE == 0);
    constexpr int BN  = DUAL ? 64 : 128;
    constexpr int WN  = BN / 8;
    constexpr int NI  = WN / 8;
    constexpr int MI  = 8;
    constexpr int TAH = BM * BK;
    constexpr int TBH = BK * BN;
    constexpr int CPB = BN / 8;

    extern __shared__ __align__(16) char smz[];
    __half* As  = (__half*)smz;
    __half* Bs  = As + NSTAGE * TAH;
    __half* B2s = Bs + NSTAGE * TBH;
    __shared__ int rIdx[BM];

    const int e = blockIdx.z;
    const int count = cntp ? min(cntp[e], CAP) : fixedCount;
    const int m0 = blockIdx.y * BM;
    if (m0 >= count) return;
    const int n0 = blockIdx.x * BN;
    const int tid = threadIdx.x;

    const __half* A  = A0 + (size_t)e * strideA;
    const __half* B1 = B1g + (size_t)e * strideB;
    const __half* B2 = DUAL ? (B2g + (size_t)e * strideB) : B1g;

    if (tid < BM) {
        const int mg = m0 + tid;
        int r = -1;
        if (mg < count) r = gather ? gather[e * CAP + mg] : mg;
        rIdx[tid] = r;
    }
    __syncthreads();

    auto loadA = [&](int buf, int kt) {
        const int k0 = kt * BK;
        #pragma unroll
        for (int i = 0; i < 4; i++) {
            const int li = tid + i * 256;
            const int m = li >> 3, kg = li & 7;
            __half* dst = As + buf * TAH + m * BK + ((kg ^ (m & 7)) << 3);
            const int r = rIdx[m];
            const __half* src = A + (size_t)max(r, 0) * lda + k0 + kg * 8;
            cp16(dst, src, r >= 0);
        }
    };
    auto loadB = [&](const __half* Bg, __half* Bsb, int buf, int kt) {
        const int k0 = kt * BK;
        #pragma unroll
        for (int i = 0; i < CPB / 4; i++) {
            const int li = tid + i * 256;
            const int k = li / CPB, gc = li % CPB;
            __half* dst = Bsb + buf * TBH + k * BN + ((gc ^ (k & 7)) << 3);
            const __half* src = Bg + (size_t)(k0 + k) * ldb + n0 + gc * 8;
            cp16(dst, src, true);
        }
    };

    const int warp = tid >> 5, lane = tid & 31;
    const int wn = warp;
    const int lr = lane >> 2, lc = lane & 3;
    const int lrow = lane & 7, lmat = lane >> 3;

    uint32_t arow[MI];
    #pragma unroll
    for (int mi = 0; mi < MI; mi++)
        arow[mi] = (uint32_t)(mi * 16 + (lmat & 1) * 8 + lrow) * (BK * 2);
    const uint32_t AsU = (uint32_t)__cvta_generic_to_shared(As);
    const uint32_t BsU = (uint32_t)__cvta_generic_to_shared(Bs);
    const uint32_t B2U = (uint32_t)__cvta_generic_to_shared(B2s);

    float acc[MI][NI][4];
    float acc2[MI][NI][4];
    #pragma unroll
    for (int mi = 0; mi < MI; mi++)
        #pragma unroll
        for (int ni = 0; ni < NI; ni++)
            #pragma unroll
            for (int q = 0; q < 4; q++) {
                acc[mi][ni][q] = 0.f;
                if constexpr (DUAL) acc2[mi][ni][q] = 0.f;
            }

    const int nK = Ktot / BK;

    #pragma unroll
    for (int p = 0; p < NSTAGE - 1; p++) {
        if (p < nK) {
            loadA(p, p); loadB(B1, Bs, p, p);
            if constexpr (DUAL) loadB(B2, B2s, p, p);
        }
        asm volatile("cp.async.commit_group;\n");
    }

    for (int kt = 0; kt < nK; kt++) {
        asm volatile("cp.async.wait_group %0;\n" :: "n"(NSTAGE - 2));
        __syncthreads();
        const int ldst = kt + NSTAGE - 1;
        if (ldst < nK) {
            const int lb = ldst % NSTAGE;
            loadA(lb, ldst); loadB(B1, Bs, lb, ldst);
            if constexpr (DUAL) loadB(B2, B2s, lb, ldst);
        }
        asm volatile("cp.async.commit_group;\n");

        const int buf = kt % NSTAGE;
        const uint32_t AbU  = AsU + buf * TAH * 2;
        const uint32_t B1bU = BsU + buf * TBH * 2;
        const uint32_t B2bU = B2U + buf * TBH * 2;

        #pragma unroll
        for (int s = 0; s < 4; s++) {
            const int krow = s * 16 + (lane & 15);
            uint32_t bf[NI][2], cf[DUAL ? NI : 1][2];
            if constexpr (DUAL) {
                const uint32_t ba = (uint32_t)(krow * (BN * 2) + ((wn ^ (krow & 7)) << 4));
                LDSMT2(bf[0][0], bf[0][1], B1bU + ba);
                LDSMT2(cf[0][0], cf[0][1], B2bU + ba);
            } else {
                const int gn = wn * 2 + (lane >> 4);
                const uint32_t ba = (uint32_t)(krow * (BN * 2) + ((gn ^ (krow & 7)) << 4));
                LDSMT4(bf[0][0], bf[0][1], bf[1][0], bf[1][1], B1bU + ba);
            }
            const uint32_t gsel = (uint32_t)((2 * s + (lmat >> 1)) ^ lrow);
            #pragma unroll
            for (int mi = 0; mi < MI; mi++) {
                uint32_t a0, a1, a2, a3;
                LDSM4(a0, a1, a2, a3, AbU + arow[mi] + gsel * 16u);
                #pragma unroll
                for (int ni = 0; ni < NI; ni++) {
                    mma_f16(acc[mi][ni], a0, a1, a2, a3, bf[ni][0], bf[ni][1]);
                    if constexpr (DUAL)
                        mma_f16(acc2[mi][ni], a0, a1, a2, a3, cf[ni][0], cf[ni][1]);
                }
            }
        }
    }

    // epilogue
    #pragma unroll
    for (int mi = 0; mi < MI; mi++) {
        const int rbase = mi * 16 + lr;
        #pragma unroll
        for (int half = 0; half < 2; half++) {
            const int r = rbase + half * 8;
            const int mg = m0 + r;
            const bool valid = (mg < count);
            #pragma unroll
            for (int ni = 0; ni < NI; ni++) {
                const int n = n0 + wn * WN + ni * 8 + lc * 2;
                const float c0 = acc[mi][ni][half * 2 + 0];
                const float c1 = acc[mi][ni][half * 2 + 1];
                if constexpr (MODE == 0) {
                    if (valid) {
                        const float u0 = acc2[mi][ni][half * 2 + 0];
                        const float u1 = acc2[mi][ni][half * 2 + 1];
                        const float h0 = (c0 / (1.f + __expf(-c0))) * u0;
                        const float h1 = (c1 / (1.f + __expf(-c1))) * u1;
                        __half* dst = (__half*)C0 + (size_t)e * strideC + (size_t)mg * ldc + n;
                        *reinterpret_cast<uint32_t*>(dst) = packh2(h0, h1);
                    }
                } else if constexpr (MODE == 1) {
                    if (valid) {
                        const int tok = g_slot_tok[e * CAP + mg];
                        const float w = g_slot_w[e * CAP + mg];
                        float* dst = outp + (size_t)tok * HDIM + n;
                        asm volatile("red.global.add.v2.f32 [%0], {%1, %2};"
                                     :: "l"(dst), "f"(w * c0), "f"(w * c1) : "memory");
                    }
                } else {
                    if (valid) {
                        const float sg = g_sgate[mg];
                        float* dst = (float*)C0 + (size_t)mg * ldc + n;
                        asm volatile("red.global.add.v2.f32 [%0], {%1, %2};"
                                     :: "l"(dst), "f"(sg * c0), "f"(sg * c1) : "memory");
                    }
                }
            }
        }
    }
}

// ---------------- launcher ---------------------------------------------------
static void cvt16(const float* src, __half* dst, size_t n, cudaStream_t st) {
    const int n8 = (int)(n / 8);
    cvt16_kernel<<<(n8 + 255) / 256, 256, 0, st>>>(
        (const float4*)src, (uint4*)dst, n8);
}

extern "C" void kernel_launch(void* const* d_in, const int* in_sizes, int n_in,
                              void* d_out, int out_size)
{
    const float* x       = (const float*)d_in[0];
    const float* gate_w  = (const float*)d_in[1];
    const float* w_gate  = (const float*)d_in[2];
    const float* w_up    = (const float*)d_in[3];
    const float* w_down  = (const float*)d_in[4];
    const float* ws_gate = (const float*)d_in[5];
    const float* ws_up   = (const float*)d_in[6];
    const float* ws_down = (const float*)d_in[7];
    const float* w_sg    = (const float*)d_in[8];
    float* out    = (float*)d_out;
    float* logits = out + (size_t)T_TOK * HDIM;

    const int SMEM  = NSTAGE * (BM * BK + 2 * BK * 64) * 2;   // MODE0: 96KB
    const int SMEM2 = NSTAGE * (BM * BK + BK * 128) * 2;      // MODE1/2: 96KB

    // one-time resource setup (handles persist; no allocations on later calls,
    // in particular none during the harness's graph-capture call)
    static bool s_init = false;
    static cudaStream_t s1, s2, s3;
    static cudaEvent_t ev0, evS2, evDisp, evWd, ev1;
    if (!s_init) {
        cudaFuncSetAttribute((const void*)moe_gemm<0>, cudaFuncAttributeMaxDynamicSharedMemorySize, SMEM);
        cudaFuncSetAttribute((const void*)moe_gemm<1>, cudaFuncAttributeMaxDynamicSharedMemorySize, SMEM2);
        cudaFuncSetAttribute((const void*)moe_gemm<2>, cudaFuncAttributeMaxDynamicSharedMemorySize, SMEM2);
        cudaStreamCreateWithFlags(&s1, cudaStreamNonBlocking);
        cudaStreamCreateWithFlags(&s2, cudaStreamNonBlocking);
        cudaStreamCreateWithFlags(&s3, cudaStreamNonBlocking);
        cudaEventCreateWithFlags(&ev0,   cudaEventDisableTiming);
        cudaEventCreateWithFlags(&evS2,  cudaEventDisableTiming);
        cudaEventCreateWithFlags(&evDisp, cudaEventDisableTiming);
        cudaEventCreateWithFlags(&evWd,  cudaEventDisableTiming);
        cudaEventCreateWithFlags(&ev1,   cudaEventDisableTiming);
        s_init = true;
    }

    __half *x16, *wg16, *wu16, *wd16, *wsg16, *wsu16, *wsd16, *h16, *hs16;
    cudaGetSymbolAddress((void**)&x16,  g_x16);
    cudaGetSymbolAddress((void**)&wg16, g_wg16);
    cudaGetSymbolAddress((void**)&wu16, g_wu16);
    cudaGetSymbolAddress((void**)&wd16, g_wd16);
    cudaGetSymbolAddress((void**)&wsg16, g_wsg16);
    cudaGetSymbolAddress((void**)&wsu16, g_wsu16);
    cudaGetSymbolAddress((void**)&wsd16, g_wsd16);
    cudaGetSymbolAddress((void**)&h16,  g_h16);
    cudaGetSymbolAddress((void**)&hs16, g_hs16);
    int* counts; cudaGetSymbolAddress((void**)&counts, g_counts);
    int* slots;  cudaGetSymbolAddress((void**)&slots,  g_slot_tok);

    // fork
    cudaEventRecord(ev0, 0);
    cudaStreamWaitEvent(s1, ev0, 0);
    cudaStreamWaitEvent(s2, ev0, 0);
    cudaStreamWaitEvent(s3, ev0, 0);

    // stream 0: zero out + routing
    const int n4out = (T_TOK * HDIM + T_TOK * NEXP) / 4;
    zero_out_kernel<<<(n4out + 255) / 256, 256>>>((float4*)out, n4out);
    zero_counts_kernel<<<1, 32>>>();
    router_kernel<<<T_TOK, 128>>>(x, gate_w, w_sg, logits);
    dispatch_kernel<<<(T_TOK * TOPK + 255) / 256, 256>>>();
    cudaEventRecord(evDisp, 0);

    // s2: light conversions (x + shared-expert weights)
    cvt16(x,       x16,   (size_t)T_TOK * HDIM, s2);
    cvt16(ws_gate, wsg16, (size_t)HDIM * ISH,   s2);
    cvt16(ws_up,   wsu16, (size_t)HDIM * ISH,   s2);
    cvt16(ws_down, wsd16, (size_t)ISH * HDIM,   s2);
    cudaEventRecord(evS2, s2);

    // s1: heavy conversions (expert up/gate weights)
    cvt16(w_gate, wg16, (size_t)NEXP * HDIM * IDIM, s1);
    cvt16(w_up,   wu16, (size_t)NEXP * HDIM * IDIM, s1);

    // s3: expert down weights (overlaps E1)
    cvt16(w_down, wd16, (size_t)NEXP * IDIM * HDIM, s3);
    cudaEventRecord(evWd, s3);

    // s1: E1 (needs x16 from s2, slots from 0), then E2 (needs wd16 from s3)
    cudaStreamWaitEvent(s1, evDisp, 0);
    cudaStreamWaitEvent(s1, evS2, 0);
    moe_gemm<0><<<dim3(IDIM / 64, 2, NEXP), 256, SMEM, s1>>>(
        x16, HDIM, HDIM, wg16, wu16, IDIM, h16, IDIM,
        slots, counts, 0, nullptr,
        0L, (long)HDIM * IDIM, (long)CAP * IDIM);
    cudaStreamWaitEvent(s1, evWd, 0);
    moe_gemm<1><<<dim3(HDIM / 128, 2, NEXP), 256, SMEM2, s1>>>(
        h16, IDIM, IDIM, wd16, nullptr, HDIM, nullptr, 0,
        nullptr, counts, 0, out,
        (long)CAP * IDIM, (long)IDIM * HDIM, 0L);
    cudaEventRecord(ev1, s1);

    // stream 0: shared-expert path (needs s2 conversions)
    cudaStreamWaitEvent(0, evS2, 0);
    moe_gemm<0><<<dim3(ISH / 64, T_TOK / BM, 1), 256, SMEM>>>(
        x16, HDIM, HDIM, wsg16, wsu16, ISH, hs16, ISH,
        nullptr, nullptr, T_TOK, nullptr, 0L, 0L, 0L);
    moe_gemm<2><<<dim3(HDIM / 128, T_TOK / BM, 1), 256, SMEM2>>>(
        hs16, ISH, ISH, wsd16, nullptr, HDIM, out, HDIM,
        nullptr, nullptr, T_TOK, nullptr, 0L, 0L, 0L);

    // join expert stream back into the capture stream
    cudaStreamWaitEvent(0, ev1, 0);
}